// round 14
// baseline (speedup 1.0000x reference)
#include <cuda_runtime.h>
#include <cstdint>

#define NN 2048
#define TT 4096
#define MAXS 256
#define C_CTAS 8
#define NPC 256            /* neurons (=threads) per CTA */
#define WARPS 8            /* warps per CTA */
#define NSLOTS 64          /* total publishing warps in cluster */
#define DEPTH 8            /* slot ring depth (skew bound is 2) */
#define PF 4               /* ic/ur prefetch depth (register ring) */
#define DT 2.44140625e-4f  /* (1-0)/4096, exact in fp32 */
#define ALPHA_F 0.01f
#define FULLM 0xffffffffu

__global__ void init_kernel(float* __restrict__ out) {
    int idx = blockIdx.x * blockDim.x + threadIdx.x;
    int stride = gridDim.x * blockDim.x;
    // Output layout: [ys (T*N*3)] [tev (256)] [yev (256*N*3)] [et (256*N)] [num_spikes (1)]
    float* tev = out + (size_t)TT * NN * 3;
    const int inf_n = MAXS + MAXS * NN * 3;          // tevents + yevents -> +inf
    const float finf = __int_as_float(0x7f800000);
    for (int t = idx; t < inf_n; t += stride) tev[t] = finf;
    float* et = tev + inf_n;
    const int et_n = MAXS * NN;                      // event_types -> 0
    for (int t = idx; t < et_n; t += stride) et[t] = 0.0f;
}

__device__ __forceinline__ void ld_vol_shared_v2(unsigned addr, unsigned& a, unsigned& b) {
    asm volatile("ld.volatile.shared.v2.u32 {%0, %1}, [%2];"
                 : "=r"(a), "=r"(b) : "r"(addr));
}
__device__ __forceinline__ void st_shared_cluster(unsigned addr, unsigned v) {
    asm volatile("st.shared::cluster.u32 [%0], %1;" :: "r"(addr), "r"(v) : "memory");
}
__device__ __forceinline__ unsigned mapa_u32(unsigned addr, unsigned rank) {
    unsigned r;
    asm("mapa.shared::cluster.u32 %0, %1, %2;" : "=r"(r) : "r"(addr), "r"(rank));
    return r;
}
__device__ __forceinline__ unsigned smem_u32(const void* p) {
    unsigned a;
    asm("{ .reg .u64 t; cvta.to.shared.u64 t, %1; cvt.u32.u64 %0, t; }" : "=r"(a) : "l"(p));
    return a;
}

// Exact jax.nn.softplus(x) = max(x,0) + log1p(exp(-|x|))
__device__ __forceinline__ float softplus_ref(float v) {
    float ax = fabsf(v);
    float e  = expf(-ax);
    float l  = log1pf(e);
    return __fadd_rn(fmaxf(v, 0.0f), l);
}

// Bit-exact softplus with large-v fast path:
// for v >= 16, log1pf(expf(-v)) <= 1.1254e-7 < 0.5*ulp(v) (= 9.54e-7 in [16,32),
// growing with the binade), so fadd_rn(v, l) == v bitwise. The branch skips the
// entire MUFU chain when the whole warp is in the fast region.
__device__ __forceinline__ float softplus_fast(float v) {
    float sp = v;
    if (v < 16.0f) sp = softplus_ref(v);
    return sp;
}

__global__ void __launch_bounds__(NPC, 1) __cluster_dims__(C_CTAS, 1, 1)
sim_kernel(const float* __restrict__ w,  const float* __restrict__ mu,
           const float* __restrict__ v0, const float* __restrict__ i0,
           const float* __restrict__ ic, const float* __restrict__ u0,
           const float* __restrict__ ur, float* __restrict__ out)
{
    __shared__ __align__(16) unsigned slots[DEPTH * NSLOTS];  // [ring][64 warp slots]

    const int t    = threadIdx.x;
    const int lane = t & 31;
    const int wid  = t >> 5;
    const int cta  = blockIdx.x;                 // grid == one cluster -> rank
    const int n    = cta * NPC + t;

    const float mu1  = mu[0];
    const float nmu2 = -mu[1];
    const float dt   = DT;

    float* ys  = out;
    float* tev = out + (size_t)TT * NN * 3;
    float* yev = tev + MAXS;
    float* et  = yev + (size_t)MAXS * NN * 3;
    float* nsp = et  + (size_t)MAXS * NN;

    // zero the slot ring, then cluster-sync before anyone publishes
    for (int i = t; i < DEPTH * NSLOTS; i += NPC) slots[i] = 0u;
    const unsigned sbase = smem_u32(slots);
    // each of lanes 0..7 injects the publish into one peer CTA
    const unsigned my_peer = mapa_u32(sbase, (unsigned)(lane & 7));
    const unsigned my_slot_off = (unsigned)(cta * WARPS + wid) * 4u;
    const unsigned base_code = (unsigned)(cta * NPC + wid * 32);
    asm volatile("barrier.cluster.arrive.aligned;" ::: "memory");
    asm volatile("barrier.cluster.wait.aligned;"   ::: "memory");

    // Carried state (end of step k-1):
    float v   = v0[n];                              // v2(k-1)
    float s   = __fsub_rn(logf(u0[n]), ALPHA_F);    // s2(k-1)
    float i1c = 0.0f;                               // i1(k-1), BEFORE w-row (k>=1)
    const float i0v = i0[n];
    float v1s = 0.0f, s1s = 0.0f;                   // saved v1(k-1), s1(k-1)
    bool  maskp = false;
    int   cnt = 0;

    // prefetch ring: ic/u for steps 0..PF-1
    float icb[PF], ub[PF];
    #pragma unroll
    for (int j = 0; j < PF; ++j) {
        icb[j] = __ldg(&ic[(size_t)j * NN + n]);
        ub[j]  = __ldg(&ur[(size_t)j * NN + n]);
    }

    // ---------------- peeled k = 0 (no resolve: i2 = i0) ----------------
    {
        float sp = softplus_ref(v);
        float s1 = __fadd_rn(s, __fmul_rn(dt, sp));
        bool  mask = (s1 >= 0.0f);
        unsigned bal  = __ballot_sync(FULLM, mask);
        unsigned code = bal ? base_code + (unsigned)__ffs(bal) : 0xFFFu;
        unsigned val = (1u << 12) | code;
        if (lane < 8) st_shared_cluster(my_peer + my_slot_off, val);

        float lu  = __fsub_rn(logf(ub[0]), ALPHA_F);
        float ick = icb[0];
        icb[0] = __ldg(&ic[(size_t)PF * NN + n]);
        ub[0]  = __ldg(&ur[(size_t)PF * NN + n]);

        float t1  = __fsub_rn(__fadd_rn(i0v, ick), v);
        float v1  = __fadd_rn(v, __fmul_rn(dt, __fmul_rn(mu1, t1)));
        float i1n = __fadd_rn(i0v, __fmul_rn(dt, __fmul_rn(nmu2, i0v)));
        float v2  = mask ? __fsub_rn(v1, 1.0f) : v1;
        float s2  = mask ? lu : s1;
        v1s = v1; s1s = s1; maskp = mask;
        v = v2; i1c = i1n; s = s2;
    }

    // ---------------- main loop k = 1 .. TT-1 ----------------
    #pragma unroll 4
    for (int k = 1; k < TT; ++k) {
        const int p = k & (PF - 1);

        // ---- publish step k FIRST (needs only carried v, s) ----
        float sp = softplus_fast(v);                   // bit-exact; warp skips MUFU when v>=16
        float s1 = __fadd_rn(s, __fmul_rn(dt, sp));
        bool  mask = (s1 >= 0.0f);
        unsigned bal  = __ballot_sync(FULLM, mask);
        unsigned code = bal ? base_code + (unsigned)__ffs(bal) : 0xFFFu;
        unsigned val  = ((unsigned)(k + 1) << 12) | code;
        if (lane < 8)
            st_shared_cluster(my_peer + (unsigned)((k & (DEPTH - 1)) * NSLOTS) * 4u
                                      + my_slot_off, val);

        // ---- off-chain work while peers' publishes propagate ----
        float lu  = __fsub_rn(logf(ub[p]), ALPHA_F);   // u loaded PF steps ago
        float ick = icb[p];
        int   kp  = (k + PF < TT) ? (k + PF) : (TT - 1);
        icb[p] = __ldg(&ic[(size_t)kp * NN + n]);
        ub[p]  = __ldg(&ur[(size_t)kp * NN + n]);

        // ---- resolve step k-1: poll local smem (paired 64-bit), then w gather ----
        const unsigned want = (unsigned)k << 12;       // tag of step k-1
        const unsigned boff = sbase + (unsigned)(((k - 1) & (DEPTH - 1)) * NSLOTS) * 4u
                                    + (unsigned)lane * 8u;
        unsigned a, b;
        do { ld_vol_shared_v2(boff, a, b); }
        while (__ballot_sync(FULLM, (((a ^ want) | (b ^ want)) & 0xFFFFF000u) != 0u));
        unsigned m = __reduce_min_sync(FULLM, umin(a, b));
        unsigned ecode = m & 0xFFFu;
        bool eventp = (ecode != 0xFFFu);
        // unconditional LDG (row 0 when no event, L1-hot); select afterwards
        unsigned row = eventp ? (ecode - 1u) : 0u;
        float wraw = __ldg(&w[(size_t)row * NN + n]);
        float wv   = eventp ? wraw : 0.0f;

        float ysv = v, yss = s, i1old = i1c;
        float i2  = __fadd_rn(i1old, wv);              // +0 exact when no event

        // ---- advance to end-of-step-k state (critical chain) ----
        float t1  = __fsub_rn(__fadd_rn(i2, ick), v);
        float v1  = __fadd_rn(v, __fmul_rn(dt, __fmul_rn(mu1, t1)));
        float i1n = __fadd_rn(i2, __fmul_rn(dt, __fmul_rn(nmu2, i2)));
        float v2  = mask ? __fsub_rn(v1, 1.0f) : v1;
        float s2  = mask ? lu : s1;

        // ---- deferred outputs for step k-1 (fire-and-forget) ----
        size_t ob = ((size_t)(k - 1) * NN + n) * 3;
        ys[ob + 0] = ysv;
        ys[ob + 1] = i2;
        ys[ob + 2] = yss;
        if (eventp && cnt < MAXS) {
            size_t eb = ((size_t)cnt * NN + n) * 3;
            yev[eb + 0] = v1s;                         // pre-transition y at event step
            yev[eb + 1] = i1old;
            yev[eb + 2] = s1s;
            et[(size_t)cnt * NN + n] = maskp ? 1.0f : 0.0f;
            if (n == 0) tev[cnt] = __fmul_rn((float)k, dt);  // ((k-1)+1)*dt
            cnt++;
        }

        v1s = v1; s1s = s1; maskp = mask;
        v = v2; i1c = i1n; s = s2;
    }

    // ---------------- epilogue: resolve step TT-1 ----------------
    {
        const unsigned want = (unsigned)TT << 12;
        const unsigned boff = sbase + (unsigned)(((TT - 1) & (DEPTH - 1)) * NSLOTS) * 4u
                                    + (unsigned)lane * 8u;
        unsigned a, b;
        do { ld_vol_shared_v2(boff, a, b); }
        while (__ballot_sync(FULLM, (((a ^ want) | (b ^ want)) & 0xFFFFF000u) != 0u));
        unsigned m = __reduce_min_sync(FULLM, umin(a, b));
        unsigned ecode = m & 0xFFFu;
        bool eventp = (ecode != 0xFFFu);
        float wv = 0.0f;
        if (eventp) wv = __ldg(&w[(size_t)(ecode - 1u) * NN + n]);
        float i2 = __fadd_rn(i1c, wv);

        size_t ob = ((size_t)(TT - 1) * NN + n) * 3;
        ys[ob + 0] = v;
        ys[ob + 1] = i2;
        ys[ob + 2] = s;
        if (eventp && cnt < MAXS) {
            size_t eb = ((size_t)cnt * NN + n) * 3;
            yev[eb + 0] = v1s;
            yev[eb + 1] = i1c;
            yev[eb + 2] = s1s;
            et[(size_t)cnt * NN + n] = maskp ? 1.0f : 0.0f;
            if (n == 0) tev[cnt] = __fmul_rn((float)TT, dt);
            cnt++;
        }
    }

    if (n == 0) nsp[0] = (float)cnt;

    // no CTA may exit while peers could still address its SMEM
    asm volatile("barrier.cluster.arrive.aligned;" ::: "memory");
    asm volatile("barrier.cluster.wait.aligned;"   ::: "memory");
}

extern "C" void kernel_launch(void* const* d_in, const int* in_sizes, int n_in,
                              void* d_out, int out_size) {
    const float* w  = (const float*)d_in[0];
    const float* mu = (const float*)d_in[1];
    const float* v0 = (const float*)d_in[2];
    const float* i0 = (const float*)d_in[3];
    const float* ic = (const float*)d_in[4];
    const float* u0 = (const float*)d_in[5];
    const float* ur = (const float*)d_in[6];
    float* out = (float*)d_out;

    init_kernel<<<512, 256>>>(out);
    sim_kernel<<<C_CTAS, NPC>>>(w, mu, v0, i0, ic, u0, ur, out);
    (void)in_sizes; (void)n_in; (void)out_size;
}

// round 15
// speedup vs baseline: 1.1797x; 1.1797x over previous
#include <cuda_runtime.h>
#include <cstdint>

#define NN 2048
#define TT 4096
#define MAXS 256
#define C_CTAS 8
#define NPC 256            /* neurons (=threads) per CTA */
#define WARPS 8            /* warps per CTA */
#define NSLOTS 64          /* total publishing warps in cluster */
#define DEPTH 8            /* slot ring depth (skew bound is 2) */
#define PF 8               /* ic/ur prefetch depth (register ring) */
#define DT 2.44140625e-4f  /* (1-0)/4096, exact in fp32 */
#define ALPHA_F 0.01f
#define FULLM 0xffffffffu

__global__ void init_kernel(float* __restrict__ out) {
    int idx = blockIdx.x * blockDim.x + threadIdx.x;
    int stride = gridDim.x * blockDim.x;
    // Output layout: [ys (T*N*3)] [tev (256)] [yev (256*N*3)] [et (256*N)] [num_spikes (1)]
    float* tev = out + (size_t)TT * NN * 3;
    const int inf_n = MAXS + MAXS * NN * 3;          // tevents + yevents -> +inf
    const float finf = __int_as_float(0x7f800000);
    for (int t = idx; t < inf_n; t += stride) tev[t] = finf;
    float* et = tev + inf_n;
    const int et_n = MAXS * NN;                      // event_types -> 0
    for (int t = idx; t < et_n; t += stride) et[t] = 0.0f;
}

__device__ __forceinline__ void ld_vol_shared_v2(unsigned addr, unsigned& a, unsigned& b) {
    asm volatile("ld.volatile.shared.v2.u32 {%0, %1}, [%2];"
                 : "=r"(a), "=r"(b) : "r"(addr));
}
__device__ __forceinline__ void st_shared_cluster(unsigned addr, unsigned v) {
    asm volatile("st.shared::cluster.u32 [%0], %1;" :: "r"(addr), "r"(v) : "memory");
}
__device__ __forceinline__ unsigned mapa_u32(unsigned addr, unsigned rank) {
    unsigned r;
    asm("mapa.shared::cluster.u32 %0, %1, %2;" : "=r"(r) : "r"(addr), "r"(rank));
    return r;
}
__device__ __forceinline__ unsigned smem_u32(const void* p) {
    unsigned a;
    asm("{ .reg .u64 t; cvta.to.shared.u64 t, %1; cvt.u32.u64 %0, t; }" : "=r"(a) : "l"(p));
    return a;
}

// Exact jax.nn.softplus(x) = max(x,0) + log1p(exp(-|x|))
__device__ __forceinline__ float softplus_ref(float v) {
    float ax = fabsf(v);
    float e  = expf(-ax);
    float l  = log1pf(e);
    return __fadd_rn(fmaxf(v, 0.0f), l);
}

__global__ void __launch_bounds__(NPC, 1) __cluster_dims__(C_CTAS, 1, 1)
sim_kernel(const float* __restrict__ w,  const float* __restrict__ mu,
           const float* __restrict__ v0, const float* __restrict__ i0,
           const float* __restrict__ ic, const float* __restrict__ u0,
           const float* __restrict__ ur, float* __restrict__ out)
{
    __shared__ __align__(16) unsigned slots[DEPTH * NSLOTS];  // [ring][64 warp slots]

    const int t    = threadIdx.x;
    const int lane = t & 31;
    const int wid  = t >> 5;
    const int cta  = blockIdx.x;                 // grid == one cluster -> rank
    const int n    = cta * NPC + t;

    const float mu1  = mu[0];
    const float nmu2 = -mu[1];
    const float dt   = DT;

    float* ys  = out;
    float* tev = out + (size_t)TT * NN * 3;
    float* yev = tev + MAXS;
    float* et  = yev + (size_t)MAXS * NN * 3;
    float* nsp = et  + (size_t)MAXS * NN;

    // zero the slot ring, then cluster-sync before anyone publishes
    for (int i = t; i < DEPTH * NSLOTS; i += NPC) slots[i] = 0u;
    const unsigned sbase = smem_u32(slots);
    // each of lanes 0..7 injects the publish into one peer CTA
    const unsigned my_peer = mapa_u32(sbase, (unsigned)(lane & 7));
    const unsigned my_slot_off = (unsigned)(cta * WARPS + wid) * 4u;
    const unsigned base_code = (unsigned)(cta * NPC + wid * 32);
    asm volatile("barrier.cluster.arrive.aligned;" ::: "memory");
    asm volatile("barrier.cluster.wait.aligned;"   ::: "memory");

    // Carried state (end of step k-1):
    float v   = v0[n];                              // v2(k-1)
    float s   = __fsub_rn(logf(u0[n]), ALPHA_F);    // s2(k-1)
    float i1c = 0.0f;                               // i1(k-1), BEFORE w-row (k>=1)
    const float i0v = i0[n];
    float v1s = 0.0f, s1s = 0.0f;                   // saved v1(k-1), s1(k-1)
    bool  maskp = false;
    int   cnt = 0;

    // prefetch ring: ic/u for steps 0..PF-1
    float icb[PF], ub[PF];
    #pragma unroll
    for (int j = 0; j < PF; ++j) {
        icb[j] = __ldg(&ic[(size_t)j * NN + n]);
        ub[j]  = __ldg(&ur[(size_t)j * NN + n]);
    }

    // ---------------- peeled k = 0 (no resolve: i2 = i0) ----------------
    {
        float sp = softplus_ref(v);
        float s1 = __fadd_rn(s, __fmul_rn(dt, sp));
        bool  mask = (s1 >= 0.0f);
        unsigned bal  = __ballot_sync(FULLM, mask);
        unsigned code = bal ? base_code + (unsigned)__ffs(bal) : 0xFFFu;
        unsigned val = (1u << 12) | code;
        if (lane < 8) st_shared_cluster(my_peer + my_slot_off, val);

        float lu  = __fsub_rn(logf(ub[0]), ALPHA_F);
        float ick = icb[0];
        icb[0] = __ldg(&ic[(size_t)PF * NN + n]);
        ub[0]  = __ldg(&ur[(size_t)PF * NN + n]);

        float t1  = __fsub_rn(__fadd_rn(i0v, ick), v);
        float v1  = __fadd_rn(v, __fmul_rn(dt, __fmul_rn(mu1, t1)));
        float i1n = __fadd_rn(i0v, __fmul_rn(dt, __fmul_rn(nmu2, i0v)));
        float v2  = mask ? __fsub_rn(v1, 1.0f) : v1;
        float s2  = mask ? lu : s1;
        v1s = v1; s1s = s1; maskp = mask;
        v = v2; i1c = i1n; s = s2;
    }

    // ---------------- main loop k = 1 .. TT-1 ----------------
    #pragma unroll 8
    for (int k = 1; k < TT; ++k) {
        const int p = k & (PF - 1);

        // ---- publish step k FIRST (needs only carried v, s) ----
        float sp = softplus_ref(v);
        float s1 = __fadd_rn(s, __fmul_rn(dt, sp));
        bool  mask = (s1 >= 0.0f);
        unsigned bal  = __ballot_sync(FULLM, mask);
        unsigned code = bal ? base_code + (unsigned)__ffs(bal) : 0xFFFu;
        unsigned val  = ((unsigned)(k + 1) << 12) | code;
        if (lane < 8)
            st_shared_cluster(my_peer + (unsigned)((k & (DEPTH - 1)) * NSLOTS) * 4u
                                      + my_slot_off, val);

        // ---- off-chain work while peers' publishes propagate ----
        float lu  = __fsub_rn(logf(ub[p]), ALPHA_F);   // u loaded PF steps ago
        float ick = icb[p];
        int   kp  = (k + PF < TT) ? (k + PF) : (TT - 1);
        icb[p] = __ldg(&ic[(size_t)kp * NN + n]);
        ub[p]  = __ldg(&ur[(size_t)kp * NN + n]);

        // ---- resolve step k-1: poll local smem (paired 64-bit), then w gather ----
        const unsigned want = (unsigned)k << 12;       // tag of step k-1
        const unsigned boff = sbase + (unsigned)(((k - 1) & (DEPTH - 1)) * NSLOTS) * 4u
                                    + (unsigned)lane * 8u;
        unsigned a, b;
        do { ld_vol_shared_v2(boff, a, b); }
        while (__ballot_sync(FULLM, (((a ^ want) | (b ^ want)) & 0xFFFFF000u) != 0u));
        unsigned m = __reduce_min_sync(FULLM, umin(a, b));
        unsigned ecode = m & 0xFFFu;
        bool eventp = (ecode != 0xFFFu);
        // unconditional LDG (row 0 when no event, L1-hot); select afterwards
        unsigned row = eventp ? (ecode - 1u) : 0u;
        float wraw = __ldg(&w[(size_t)row * NN + n]);
        float wv   = eventp ? wraw : 0.0f;

        float ysv = v, yss = s, i1old = i1c;
        float i2  = __fadd_rn(i1old, wv);              // +0 exact when no event

        // ---- advance to end-of-step-k state (critical chain) ----
        float t1  = __fsub_rn(__fadd_rn(i2, ick), v);
        float v1  = __fadd_rn(v, __fmul_rn(dt, __fmul_rn(mu1, t1)));
        float i1n = __fadd_rn(i2, __fmul_rn(dt, __fmul_rn(nmu2, i2)));
        float v2  = mask ? __fsub_rn(v1, 1.0f) : v1;
        float s2  = mask ? lu : s1;

        // ---- deferred outputs for step k-1 (fire-and-forget) ----
        size_t ob = ((size_t)(k - 1) * NN + n) * 3;
        ys[ob + 0] = ysv;
        ys[ob + 1] = i2;
        ys[ob + 2] = yss;
        if (eventp && cnt < MAXS) {
            size_t eb = ((size_t)cnt * NN + n) * 3;
            yev[eb + 0] = v1s;                         // pre-transition y at event step
            yev[eb + 1] = i1old;
            yev[eb + 2] = s1s;
            et[(size_t)cnt * NN + n] = maskp ? 1.0f : 0.0f;
            if (n == 0) tev[cnt] = __fmul_rn((float)k, dt);  // ((k-1)+1)*dt
            cnt++;
        }

        v1s = v1; s1s = s1; maskp = mask;
        v = v2; i1c = i1n; s = s2;
    }

    // ---------------- epilogue: resolve step TT-1 ----------------
    {
        const unsigned want = (unsigned)TT << 12;
        const unsigned boff = sbase + (unsigned)(((TT - 1) & (DEPTH - 1)) * NSLOTS) * 4u
                                    + (unsigned)lane * 8u;
        unsigned a, b;
        do { ld_vol_shared_v2(boff, a, b); }
        while (__ballot_sync(FULLM, (((a ^ want) | (b ^ want)) & 0xFFFFF000u) != 0u));
        unsigned m = __reduce_min_sync(FULLM, umin(a, b));
        unsigned ecode = m & 0xFFFu;
        bool eventp = (ecode != 0xFFFu);
        float wv = 0.0f;
        if (eventp) wv = __ldg(&w[(size_t)(ecode - 1u) * NN + n]);
        float i2 = __fadd_rn(i1c, wv);

        size_t ob = ((size_t)(TT - 1) * NN + n) * 3;
        ys[ob + 0] = v;
        ys[ob + 1] = i2;
        ys[ob + 2] = s;
        if (eventp && cnt < MAXS) {
            size_t eb = ((size_t)cnt * NN + n) * 3;
            yev[eb + 0] = v1s;
            yev[eb + 1] = i1c;
            yev[eb + 2] = s1s;
            et[(size_t)cnt * NN + n] = maskp ? 1.0f : 0.0f;
            if (n == 0) tev[cnt] = __fmul_rn((float)TT, dt);
            cnt++;
        }
    }

    if (n == 0) nsp[0] = (float)cnt;

    // no CTA may exit while peers could still address its SMEM
    asm volatile("barrier.cluster.arrive.aligned;" ::: "memory");
    asm volatile("barrier.cluster.wait.aligned;"   ::: "memory");
}

extern "C" void kernel_launch(void* const* d_in, const int* in_sizes, int n_in,
                              void* d_out, int out_size) {
    const float* w  = (const float*)d_in[0];
    const float* mu = (const float*)d_in[1];
    const float* v0 = (const float*)d_in[2];
    const float* i0 = (const float*)d_in[3];
    const float* ic = (const float*)d_in[4];
    const float* u0 = (const float*)d_in[5];
    const float* ur = (const float*)d_in[6];
    float* out = (float*)d_out;

    init_kernel<<<512, 256>>>(out);
    sim_kernel<<<C_CTAS, NPC>>>(w, mu, v0, i0, ic, u0, ur, out);
    (void)in_sizes; (void)n_in; (void)out_size;
}

// round 16
// speedup vs baseline: 1.1962x; 1.0140x over previous
#include <cuda_runtime.h>
#include <cstdint>

#define NN 2048
#define TT 4096
#define MAXS 256
#define C_CTAS 8
#define NPC 256            /* neurons (=threads) per CTA */
#define WARPS 8            /* warps per CTA */
#define NSLOTS 64          /* total publishing warps in cluster */
#define DEPTH 8            /* slot ring depth (skew bound is 2) */
#define PF 8               /* ic/ur prefetch depth (register ring) */
#define DT 2.44140625e-4f  /* (1-0)/4096, exact in fp32 */
#define ALPHA_F 0.01f
#define FULLM 0xffffffffu

__global__ void init_kernel(float* __restrict__ out) {
    int idx = blockIdx.x * blockDim.x + threadIdx.x;
    int stride = gridDim.x * blockDim.x;
    // Output layout: [ys (T*N*3)] [tev (256)] [yev (256*N*3)] [et (256*N)] [num_spikes (1)]
    float* tev = out + (size_t)TT * NN * 3;
    const int inf_n = MAXS + MAXS * NN * 3;          // tevents + yevents -> +inf
    const float finf = __int_as_float(0x7f800000);
    for (int t = idx; t < inf_n; t += stride) tev[t] = finf;
    float* et = tev + inf_n;
    const int et_n = MAXS * NN;                      // event_types -> 0
    for (int t = idx; t < et_n; t += stride) et[t] = 0.0f;
}

__device__ __forceinline__ void ld_vol_shared_v2(unsigned addr, unsigned& a, unsigned& b) {
    asm volatile("ld.volatile.shared.v2.u32 {%0, %1}, [%2];"
                 : "=r"(a), "=r"(b) : "r"(addr));
}
__device__ __forceinline__ void st_shared_cluster(unsigned addr, unsigned v) {
    asm volatile("st.shared::cluster.u32 [%0], %1;" :: "r"(addr), "r"(v) : "memory");
}
__device__ __forceinline__ unsigned mapa_u32(unsigned addr, unsigned rank) {
    unsigned r;
    asm("mapa.shared::cluster.u32 %0, %1, %2;" : "=r"(r) : "r"(addr), "r"(rank));
    return r;
}
__device__ __forceinline__ unsigned smem_u32(const void* p) {
    unsigned a;
    asm("{ .reg .u64 t; cvta.to.shared.u64 t, %1; cvt.u32.u64 %0, t; }" : "=r"(a) : "l"(p));
    return a;
}

// Exact jax.nn.softplus(x) = max(x,0) + log1p(exp(-|x|))
__device__ __forceinline__ float softplus_ref(float v) {
    float ax = fabsf(v);
    float e  = expf(-ax);
    float l  = log1pf(e);
    return __fadd_rn(fmaxf(v, 0.0f), l);
}

__global__ void __launch_bounds__(NPC, 1) __cluster_dims__(C_CTAS, 1, 1)
sim_kernel(const float* __restrict__ w,  const float* __restrict__ mu,
           const float* __restrict__ v0, const float* __restrict__ i0,
           const float* __restrict__ ic, const float* __restrict__ u0,
           const float* __restrict__ ur, float* __restrict__ out)
{
    __shared__ __align__(16) unsigned slots[DEPTH * NSLOTS];  // [ring][64 warp slots]

    const int t    = threadIdx.x;
    const int lane = t & 31;
    const int wid  = t >> 5;
    const int cta  = blockIdx.x;                 // grid == one cluster -> rank
    const int n    = cta * NPC + t;

    const float mu1  = mu[0];
    const float nmu2 = -mu[1];
    const float dt   = DT;

    float* ys  = out;
    float* tev = out + (size_t)TT * NN * 3;
    float* yev = tev + MAXS;
    float* et  = yev + (size_t)MAXS * NN * 3;
    float* nsp = et  + (size_t)MAXS * NN;

    // zero the slot ring, then cluster-sync before anyone publishes
    for (int i = t; i < DEPTH * NSLOTS; i += NPC) slots[i] = 0u;
    const unsigned sbase = smem_u32(slots);
    // each of lanes 0..7 injects the publish into one peer CTA
    const unsigned my_peer = mapa_u32(sbase, (unsigned)(lane & 7));
    const unsigned my_slot_off = (unsigned)(cta * WARPS + wid) * 4u;
    const unsigned base_code = (unsigned)(cta * NPC + wid * 32);
    asm volatile("barrier.cluster.arrive.aligned;" ::: "memory");
    asm volatile("barrier.cluster.wait.aligned;"   ::: "memory");

    // Carried state (end of step k-1):
    float v   = v0[n];                              // v2(k-1)
    float s   = __fsub_rn(logf(u0[n]), ALPHA_F);    // s2(k-1)
    float i1c = 0.0f;                               // i1(k-1), BEFORE w-row (k>=1)
    const float i0v = i0[n];
    float v1s = 0.0f, s1s = 0.0f;                   // saved v1(k-1), s1(k-1)
    bool  maskp = false;
    int   cnt = 0;

    // prefetch ring: ic/u for steps 0..PF-1
    float icb[PF], ub[PF];
    #pragma unroll
    for (int j = 0; j < PF; ++j) {
        icb[j] = __ldg(&ic[(size_t)j * NN + n]);
        ub[j]  = __ldg(&ur[(size_t)j * NN + n]);
    }

    // ---------------- peeled k = 0 (no resolve: i2 = i0) ----------------
    {
        float sp = softplus_ref(v);
        float s1 = __fadd_rn(s, __fmul_rn(dt, sp));
        bool  mask = (s1 >= 0.0f);
        unsigned bal  = __ballot_sync(FULLM, mask);
        unsigned code = bal ? base_code + (unsigned)__ffs(bal) : 0xFFFu;
        unsigned val = (1u << 12) | code;
        if (lane < 8) st_shared_cluster(my_peer + my_slot_off, val);

        float lu  = __fsub_rn(logf(ub[0]), ALPHA_F);
        float ick = icb[0];
        icb[0] = __ldg(&ic[(size_t)PF * NN + n]);
        ub[0]  = __ldg(&ur[(size_t)PF * NN + n]);

        float t1  = __fsub_rn(__fadd_rn(i0v, ick), v);
        float v1  = __fadd_rn(v, __fmul_rn(dt, __fmul_rn(mu1, t1)));
        float i1n = __fadd_rn(i0v, __fmul_rn(dt, __fmul_rn(nmu2, i0v)));
        float v2  = mask ? __fsub_rn(v1, 1.0f) : v1;
        float s2  = mask ? lu : s1;
        v1s = v1; s1s = s1; maskp = mask;
        v = v2; i1c = i1n; s = s2;
    }

    // ---------------- main loop k = 1 .. TT-1 ----------------
    #pragma unroll 16
    for (int k = 1; k < TT; ++k) {
        const int p = k & (PF - 1);

        // ---- publish step k FIRST (needs only carried v, s) ----
        float sp = softplus_ref(v);
        float s1 = __fadd_rn(s, __fmul_rn(dt, sp));
        bool  mask = (s1 >= 0.0f);
        unsigned bal  = __ballot_sync(FULLM, mask);
        unsigned code = bal ? base_code + (unsigned)__ffs(bal) : 0xFFFu;
        unsigned val  = ((unsigned)(k + 1) << 12) | code;
        if (lane < 8)
            st_shared_cluster(my_peer + (unsigned)((k & (DEPTH - 1)) * NSLOTS) * 4u
                                      + my_slot_off, val);

        // ---- off-chain work while peers' publishes propagate ----
        float lu  = __fsub_rn(logf(ub[p]), ALPHA_F);   // u loaded PF steps ago
        float ick = icb[p];
        int   kp  = (k + PF < TT) ? (k + PF) : (TT - 1);
        icb[p] = __ldg(&ic[(size_t)kp * NN + n]);
        ub[p]  = __ldg(&ur[(size_t)kp * NN + n]);

        // ---- resolve step k-1: poll local smem (paired 64-bit), then w gather ----
        const unsigned want = (unsigned)k << 12;       // tag of step k-1
        const unsigned boff = sbase + (unsigned)(((k - 1) & (DEPTH - 1)) * NSLOTS) * 4u
                                    + (unsigned)lane * 8u;
        unsigned a, b;
        do { ld_vol_shared_v2(boff, a, b); }
        while (__ballot_sync(FULLM, (((a ^ want) | (b ^ want)) & 0xFFFFF000u) != 0u));
        unsigned m = __reduce_min_sync(FULLM, umin(a, b));
        unsigned ecode = m & 0xFFFu;
        bool eventp = (ecode != 0xFFFu);
        // unconditional LDG (row 0 when no event, L1-hot); select afterwards
        unsigned row = eventp ? (ecode - 1u) : 0u;
        float wraw = __ldg(&w[(size_t)row * NN + n]);
        float wv   = eventp ? wraw : 0.0f;

        float ysv = v, yss = s, i1old = i1c;
        float i2  = __fadd_rn(i1old, wv);              // +0 exact when no event

        // ---- advance to end-of-step-k state (critical chain) ----
        float t1  = __fsub_rn(__fadd_rn(i2, ick), v);
        float v1  = __fadd_rn(v, __fmul_rn(dt, __fmul_rn(mu1, t1)));
        float i1n = __fadd_rn(i2, __fmul_rn(dt, __fmul_rn(nmu2, i2)));
        float v2  = mask ? __fsub_rn(v1, 1.0f) : v1;
        float s2  = mask ? lu : s1;

        // ---- deferred outputs for step k-1 (fire-and-forget) ----
        size_t ob = ((size_t)(k - 1) * NN + n) * 3;
        ys[ob + 0] = ysv;
        ys[ob + 1] = i2;
        ys[ob + 2] = yss;
        if (eventp && cnt < MAXS) {
            size_t eb = ((size_t)cnt * NN + n) * 3;
            yev[eb + 0] = v1s;                         // pre-transition y at event step
            yev[eb + 1] = i1old;
            yev[eb + 2] = s1s;
            et[(size_t)cnt * NN + n] = maskp ? 1.0f : 0.0f;
            if (n == 0) tev[cnt] = __fmul_rn((float)k, dt);  // ((k-1)+1)*dt
            cnt++;
        }

        v1s = v1; s1s = s1; maskp = mask;
        v = v2; i1c = i1n; s = s2;
    }

    // ---------------- epilogue: resolve step TT-1 ----------------
    {
        const unsigned want = (unsigned)TT << 12;
        const unsigned boff = sbase + (unsigned)(((TT - 1) & (DEPTH - 1)) * NSLOTS) * 4u
                                    + (unsigned)lane * 8u;
        unsigned a, b;
        do { ld_vol_shared_v2(boff, a, b); }
        while (__ballot_sync(FULLM, (((a ^ want) | (b ^ want)) & 0xFFFFF000u) != 0u));
        unsigned m = __reduce_min_sync(FULLM, umin(a, b));
        unsigned ecode = m & 0xFFFu;
        bool eventp = (ecode != 0xFFFu);
        float wv = 0.0f;
        if (eventp) wv = __ldg(&w[(size_t)(ecode - 1u) * NN + n]);
        float i2 = __fadd_rn(i1c, wv);

        size_t ob = ((size_t)(TT - 1) * NN + n) * 3;
        ys[ob + 0] = v;
        ys[ob + 1] = i2;
        ys[ob + 2] = s;
        if (eventp && cnt < MAXS) {
            size_t eb = ((size_t)cnt * NN + n) * 3;
            yev[eb + 0] = v1s;
            yev[eb + 1] = i1c;
            yev[eb + 2] = s1s;
            et[(size_t)cnt * NN + n] = maskp ? 1.0f : 0.0f;
            if (n == 0) tev[cnt] = __fmul_rn((float)TT, dt);
            cnt++;
        }
    }

    if (n == 0) nsp[0] = (float)cnt;

    // no CTA may exit while peers could still address its SMEM
    asm volatile("barrier.cluster.arrive.aligned;" ::: "memory");
    asm volatile("barrier.cluster.wait.aligned;"   ::: "memory");
}

extern "C" void kernel_launch(void* const* d_in, const int* in_sizes, int n_in,
                              void* d_out, int out_size) {
    const float* w  = (const float*)d_in[0];
    const float* mu = (const float*)d_in[1];
    const float* v0 = (const float*)d_in[2];
    const float* i0 = (const float*)d_in[3];
    const float* ic = (const float*)d_in[4];
    const float* u0 = (const float*)d_in[5];
    const float* ur = (const float*)d_in[6];
    float* out = (float*)d_out;

    init_kernel<<<512, 256>>>(out);
    sim_kernel<<<C_CTAS, NPC>>>(w, mu, v0, i0, ic, u0, ur, out);
    (void)in_sizes; (void)n_in; (void)out_size;
}